// round 4
// baseline (speedup 1.0000x reference)
#include <cuda_runtime.h>
#include <math.h>

#define NXD 32
#define HID 256
#define NOUT 528
#define BM 64
#define NTHREADS 1024
#define KC 8
#define HSTR 66
#define LSTRIDE 529

// shared layout (float offsets)
#define OFF_H2 0                    // 256 x 66 = 16896
#define OFF_W0 16896                // 8 x 256 = 2048
#define OFF_W1 18944                // 8 x 256 = 2048  (W0+W1 also reused as 256x16 tail)
#define OFF_Q  20992                // 1024
#define OFF_X  22016                // 32 x 66 = 2112   (dead after G1)
#define OFF_H1 24128                // 256 x 66 = 16896 (dead after G2)
#define OFF_L  22016                // 64 x 529 = 33856, overlays X+H1
#define SMEM_FLOATS 55872           // 223488 bytes

typedef unsigned long long u64;

__device__ __forceinline__ u64 pk2(float lo, float hi) {
    u64 d; asm("mov.b64 %0, {%1, %2};" : "=l"(d) : "f"(lo), "f"(hi)); return d;
}
__device__ __forceinline__ void fma2(u64& d, u64 a, u64 b) {
    asm("fma.rn.f32x2 %0, %1, %2, %0;" : "+l"(d) : "l"(a), "l"(b));
}
__device__ __forceinline__ float2 up2(u64 d) {
    float2 r; asm("mov.b64 {%0, %1}, %2;" : "=f"(r.x), "=f"(r.y) : "l"(d)); return r;
}
__device__ __forceinline__ float ftanh(float x) {
    x = fminf(fmaxf(x, -15.f), 15.f);
    float e = __expf(2.f * x);
    return __fdividef(e - 1.f, e + 1.f);
}
__device__ __forceinline__ float fsplus(float v) {
    float sp = (v > 20.f) ? v : __logf(1.f + __expf(v));
    return fminf(fmaxf(sp + 0.01f, 0.01f), 100.f);
}

// stage one 8x256 chunk: 1024 threads x float2
__device__ __forceinline__ void stage_ld(const float* __restrict__ Wg, int ldw,
                                         int ch, float2& rg) {
    int r = threadIdx.x >> 7, c2 = threadIdx.x & 127;
    rg = *(const float2*)&Wg[(size_t)(ch * 8 + r) * ldw + 2 * c2];
}
__device__ __forceinline__ void stage_st(float* buf, float2 rg) {
    int r = threadIdx.x >> 7, c2 = threadIdx.x & 127;
    *(float2*)&buf[r * 256 + 2 * c2] = rg;
}

// Warp tile: 16 samples (group sg) x 32 cols (group cg).
// Lane: si = tx&7 -> samples {16sg+2si, +1};  cj = tx>>3 -> cols {32cg+4cj..+3, 32cg+16+4cj..+3}
// MODE 0: tanh -> transposed outp[c*HSTR + s]
// MODE 1: GEMM3 cols [0,256): diag (cg==0) softplus else 0.1*tanh -> sL[s*529 + c]
// MODE 2: GEMM3 cols [256,512): 0.1*tanh -> sL[s*529 + 256 + c]
template<int KTOT, int MODE>
__device__ __forceinline__ void gemm_f2(
    float* sm, const float* __restrict__ Wg, int ldw,
    const float* __restrict__ bias,
    const float* sHin, float* outp, int si, int cj, int sg, int cg)
{
    const int NCH = KTOT / KC;
    const int cA = 32 * cg + 4 * cj;        // first col quad
    const int cB = cA + 16;                  // second col quad
    const int sbase = 16 * sg + 2 * si;

    u64 acc[2][4];
    {
        float4 bA = *(const float4*)&bias[cA];
        float4 bB = *(const float4*)&bias[cB];
        u64 p0 = pk2(bA.x, bA.y), p1 = pk2(bA.z, bA.w);
        u64 p2 = pk2(bB.x, bB.y), p3 = pk2(bB.z, bB.w);
        acc[0][0] = p0; acc[0][1] = p1; acc[0][2] = p2; acc[0][3] = p3;
        acc[1][0] = p0; acc[1][1] = p1; acc[1][2] = p2; acc[1][3] = p3;
    }

    float* buf0 = sm + OFF_W0;
    float* buf1 = sm + OFF_W1;
    float2 rg;
    stage_ld(Wg, ldw, 0, rg);
    stage_st(buf0, rg);
    __syncthreads();

    for (int ch = 0; ch < NCH; ch++) {
        const float* cur = (ch & 1) ? buf1 : buf0;
        float* nxt = (ch & 1) ? buf0 : buf1;
        if (ch + 1 < NCH) stage_ld(Wg, ldw, ch + 1, rg);
        const int kc = ch * KC;
        #pragma unroll
        for (int kk = 0; kk < KC; kk++) {
            float2 hx = *(const float2*)&sHin[(kc + kk) * HSTR + sbase];
            u64 h0 = pk2(hx.x, hx.x), h1 = pk2(hx.y, hx.y);
            const float* wk = cur + kk * 256;
            ulonglong2 wA = *(const ulonglong2*)(wk + cA);
            ulonglong2 wB = *(const ulonglong2*)(wk + cB);
            fma2(acc[0][0], h0, wA.x); fma2(acc[0][1], h0, wA.y);
            fma2(acc[0][2], h0, wB.x); fma2(acc[0][3], h0, wB.y);
            fma2(acc[1][0], h1, wA.x); fma2(acc[1][1], h1, wA.y);
            fma2(acc[1][2], h1, wB.x); fma2(acc[1][3], h1, wB.y);
        }
        if (ch + 1 < NCH) stage_st(nxt, rg);
        __syncthreads();
    }

    // epilogue
    #pragma unroll
    for (int ss = 0; ss < 2; ss++) {
        const int s = sbase + ss;
        #pragma unroll
        for (int p = 0; p < 2; p++) {
            const int cb = (p == 0) ? cA : cB;
            float2 v0 = up2(acc[ss][2 * p]);
            float2 v1 = up2(acc[ss][2 * p + 1]);
            float v[4] = { v0.x, v0.y, v1.x, v1.y };
            if (MODE == 0) {
                #pragma unroll
                for (int m = 0; m < 4; m++)
                    outp[(cb + m) * HSTR + s] = ftanh(v[m]);
            } else if (MODE == 1) {
                bool dg = (cg == 0);   // cols 0..31 = diag path, warp-uniform
                #pragma unroll
                for (int m = 0; m < 4; m++)
                    outp[s * LSTRIDE + cb + m] = dg ? fsplus(v[m]) : 0.1f * ftanh(v[m]);
            } else {
                #pragma unroll
                for (int m = 0; m < 4; m++)
                    outp[s * LSTRIDE + 256 + cb + m] = 0.1f * ftanh(v[m]);
            }
        }
    }
}

__global__ void __launch_bounds__(NTHREADS, 1) covnet_kernel(
    const float* __restrict__ P_prev,
    const float* __restrict__ W1, const float* __restrict__ b1,
    const float* __restrict__ W2, const float* __restrict__ b2,
    const float* __restrict__ W3, const float* __restrict__ b3,
    const float* __restrict__ Q, float* __restrict__ out)
{
    extern __shared__ float sm[];
    const int tid = threadIdx.x;
    const int tx = tid & 31;
    const int wp = tid >> 5;
    const int si = tx & 7, cj = tx >> 3;
    const int sg = wp & 3, cg = wp >> 2;
    const size_t b0 = (size_t)blockIdx.x * BM;

    // Q -> smem
    if (tid < NXD * NXD) sm[OFF_Q + tid] = Q[tid];

    // gather diagonal (transposed): sXt[d*66 + s] = log(clip(P_prev[s,d,d]))
    for (int i = tid; i < NXD * BM; i += NTHREADS) {
        int d = i >> 6, s = i & 63;
        float v = P_prev[(b0 + (size_t)s) * 1024 + d * 33];
        sm[OFF_X + d * HSTR + s] = __logf(fmaxf(v, 1e-6f));
    }
    __syncthreads();

    gemm_f2<32,  0>(sm, W1,       HID,  b1,       sm + OFF_X,  sm + OFF_H1, si, cj, sg, cg);
    gemm_f2<256, 0>(sm, W2,       HID,  b2,       sm + OFF_H1, sm + OFF_H2, si, cj, sg, cg);
    gemm_f2<256, 1>(sm, W3,       NOUT, b3,       sm + OFF_H2, sm + OFF_L,  si, cj, sg, cg);
    gemm_f2<256, 2>(sm, W3 + 256, NOUT, b3 + 256, sm + OFF_H2, sm + OFF_L,  si, cj, sg, cg);
    __syncthreads();   // W bufs about to be overwritten by tail staging

    // ====== GEMM3 tail: cols [512, 528) ======
    {
        // stage W3 tail [256 x 16] into W buffers (4096 floats)
        {
            int k = tid >> 2, c4 = tid & 3;
            float4 w = *(const float4*)&W3[(size_t)k * NOUT + 512 + 4 * c4];
            *(float4*)&sm[OFF_W0 + k * 16 + 4 * c4] = w;
        }
        __syncthreads();
        const int s = tid >> 4;       // 0..63
        const int c = tid & 15;
        float a = b3[512 + c];
        const float* hr = sm + OFF_H2;
        const float* wt = sm + OFF_W0;
        #pragma unroll 8
        for (int k = 0; k < HID; k++)
            a += hr[k * HSTR + s] * wt[k * 16 + c];
        sm[OFF_L + s * LSTRIDE + 512 + c] = 0.1f * ftanh(a);
    }
    __syncthreads();

    // ================= P = L * L^T + Q =================
    // warp handles 2 samples; lane k owns output column k.
    {
        const int k = tx;
        const int kbase = 32 + (k * (k - 1)) / 2;
        #pragma unroll
        for (int ss = 0; ss < 2; ss++) {
            const int s = 2 * wp + ss;
            const float* Lr = sm + OFF_L + s * LSTRIDE;
            float Lk[32];
            #pragma unroll
            for (int j = 0; j < 32; j++) {
                float v = 0.f;
                if (j < k)       v = Lr[kbase + j];
                else if (j == k) v = Lr[k];
                Lk[j] = v;
            }
            float* Po = out + (b0 + (size_t)s) * 1024;
            #pragma unroll
            for (int i = 0; i < 32; i++) {
                float a = sm[OFF_Q + i * 32 + k];
                const int ib = 32 + (i * (i - 1)) / 2;
                #pragma unroll
                for (int j = 0; j < i; j++) {
                    float lij = Lr[ib + j];      // warp-uniform broadcast
                    if (j <= k) a += lij * Lk[j];
                }
                float lii = Lr[i];
                if (i <= k) a += lii * Lk[i];
                Po[i * 32 + k] = a;
            }
        }
    }
}

extern "C" void kernel_launch(void* const* d_in, const int* in_sizes, int n_in,
                              void* d_out, int out_size) {
    const float* P_prev = (const float*)d_in[0];
    const float* W1 = (const float*)d_in[1];
    const float* b1 = (const float*)d_in[2];
    const float* W2 = (const float*)d_in[3];
    const float* b2 = (const float*)d_in[4];
    const float* W3 = (const float*)d_in[5];
    const float* b3 = (const float*)d_in[6];
    const float* Q  = (const float*)d_in[7];
    float* out = (float*)d_out;

    const int B = in_sizes[0] / (NXD * NXD);   // 65536
    const int grid = B / BM;                   // 1024

    cudaFuncSetAttribute(covnet_kernel,
                         cudaFuncAttributeMaxDynamicSharedMemorySize,
                         SMEM_FLOATS * sizeof(float));

    covnet_kernel<<<grid, NTHREADS, SMEM_FLOATS * sizeof(float)>>>(
        P_prev, W1, b1, W2, b2, W3, b3, Q, out);
}

// round 5
// speedup vs baseline: 1.0477x; 1.0477x over previous
#include <cuda_runtime.h>
#include <math.h>

#define NXD 32
#define HID 256
#define NOUT 528
#define BM 64
#define NTHREADS 512
#define KC 8
#define HSTR 68
#define LSTRIDE 532

// shared layout (float offsets)
#define OFF_H2 0                    // 256 x 68 = 17408
#define OFF_W0 17408                // 8 x 256 = 2048
#define OFF_W1 19456                // 8 x 256 = 2048 (W0+W1 reused as 256x16 tail)
#define OFF_Q  21504                // 1024
#define OFF_X  22528                // 32 x 68 = 2176   (dead after G1)
#define OFF_H1 24704                // 256 x 68 = 17408 (dead after G2)
#define OFF_L  22528                // 64 x 532 = 34048, overlays X+H1
#define SMEM_FLOATS 56576           // 226304 bytes

typedef unsigned long long u64;

__device__ __forceinline__ u64 pk2(float lo, float hi) {
    u64 d; asm("mov.b64 %0, {%1, %2};" : "=l"(d) : "f"(lo), "f"(hi)); return d;
}
__device__ __forceinline__ void fma2(u64& d, u64 a, u64 b) {
    asm("fma.rn.f32x2 %0, %1, %2, %0;" : "+l"(d) : "l"(a), "l"(b));
}
__device__ __forceinline__ float2 up2(u64 d) {
    float2 r; asm("mov.b64 {%0, %1}, %2;" : "=f"(r.x), "=f"(r.y) : "l"(d)); return r;
}
__device__ __forceinline__ float ftanh(float x) {
    x = fminf(fmaxf(x, -15.f), 15.f);
    float e = __expf(2.f * x);
    return __fdividef(e - 1.f, e + 1.f);
}
__device__ __forceinline__ float fsplus(float v) {
    float sp = (v > 20.f) ? v : __logf(1.f + __expf(v));
    return fminf(fmaxf(sp + 0.01f, 0.01f), 100.f);
}

// stage one 8x256 chunk (2048 floats): 512 threads x float4
__device__ __forceinline__ void stage_ld(const float* __restrict__ Wg, int ldw,
                                         int ch, float4& rg) {
    int r = threadIdx.x >> 6, c4 = threadIdx.x & 63;
    rg = *(const float4*)&Wg[(size_t)(ch * 8 + r) * ldw + 4 * c4];
}
__device__ __forceinline__ void stage_st(float* buf, float4 rg) {
    int r = threadIdx.x >> 6, c4 = threadIdx.x & 63;
    *(float4*)&buf[r * 256 + 4 * c4] = rg;
}

// Warp tile: 32 samples (sg=wp&1) x 32 cols (cg=wp>>1).
// Lane grid: r = tx&7 -> samples sbase=32sg+4r..+3 ; c = tx>>3 -> cols cbase=32cg+8c..+7
// acc[m][j]: sample m (0..3) x colpair j (0..3).
// MODE 0: tanh -> transposed outp[col*HSTR + s]
// MODE 1: GEMM3 cols [0,256): cg==0 -> softplus else 0.1*tanh -> sL[s*LSTRIDE + col]
// MODE 2: GEMM3 cols [256,512): 0.1*tanh -> sL[s*LSTRIDE + 256 + col]
template<int KTOT, int MODE>
__device__ __forceinline__ void gemm_f2(
    float* sm, const float* __restrict__ Wg, int ldw,
    const float* __restrict__ bias,
    const float* sHin, float* outp, int sbase, int cbase, int cg)
{
    const int NCH = KTOT / KC;

    u64 acc[4][4];
    {
        float4 bA = *(const float4*)&bias[cbase];
        float4 bB = *(const float4*)&bias[cbase + 4];
        u64 p0 = pk2(bA.x, bA.y), p1 = pk2(bA.z, bA.w);
        u64 p2 = pk2(bB.x, bB.y), p3 = pk2(bB.z, bB.w);
        #pragma unroll
        for (int m = 0; m < 4; m++) {
            acc[m][0] = p0; acc[m][1] = p1; acc[m][2] = p2; acc[m][3] = p3;
        }
    }

    float* buf0 = sm + OFF_W0;
    float* buf1 = sm + OFF_W1;
    float4 rg;
    stage_ld(Wg, ldw, 0, rg);
    stage_st(buf0, rg);
    __syncthreads();

    for (int ch = 0; ch < NCH; ch++) {
        const float* cur = (ch & 1) ? buf1 : buf0;
        float* nxt = (ch & 1) ? buf0 : buf1;
        if (ch + 1 < NCH) stage_ld(Wg, ldw, ch + 1, rg);
        const int kc = ch * KC;
        #pragma unroll
        for (int kk = 0; kk < KC; kk++) {
            float4 h4 = *(const float4*)&sHin[(kc + kk) * HSTR + sbase];
            u64 hd[4] = { pk2(h4.x, h4.x), pk2(h4.y, h4.y),
                          pk2(h4.z, h4.z), pk2(h4.w, h4.w) };
            const float* wk = cur + kk * 256 + cbase;
            ulonglong2 wlo = *(const ulonglong2*)wk;
            ulonglong2 whi = *(const ulonglong2*)(wk + 4);
            #pragma unroll
            for (int m = 0; m < 4; m++) {
                fma2(acc[m][0], hd[m], wlo.x);
                fma2(acc[m][1], hd[m], wlo.y);
                fma2(acc[m][2], hd[m], whi.x);
                fma2(acc[m][3], hd[m], whi.y);
            }
        }
        if (ch + 1 < NCH) stage_st(nxt, rg);
        __syncthreads();
    }

    // epilogue: lane has samples sbase..+3, cols cbase..+7
    if (MODE == 0) {
        #pragma unroll
        for (int j = 0; j < 4; j++) {      // colpair j -> cols cbase+2j, +2j+1
            float2 v0 = up2(acc[0][j]), v1 = up2(acc[1][j]);
            float2 v2 = up2(acc[2][j]), v3 = up2(acc[3][j]);
            float4 oA = { ftanh(v0.x), ftanh(v1.x), ftanh(v2.x), ftanh(v3.x) };
            float4 oB = { ftanh(v0.y), ftanh(v1.y), ftanh(v2.y), ftanh(v3.y) };
            *(float4*)&outp[(cbase + 2 * j) * HSTR + sbase]     = oA;
            *(float4*)&outp[(cbase + 2 * j + 1) * HSTR + sbase] = oB;
        }
    } else {
        #pragma unroll
        for (int m = 0; m < 4; m++) {
            const int s = sbase + m;
            float o[8];
            #pragma unroll
            for (int j = 0; j < 4; j++) {
                float2 v = up2(acc[m][j]);
                if (MODE == 1 && cg == 0) {        // warp-uniform diag path
                    o[2*j]   = fsplus(v.x);
                    o[2*j+1] = fsplus(v.y);
                } else {
                    o[2*j]   = 0.1f * ftanh(v.x);
                    o[2*j+1] = 0.1f * ftanh(v.y);
                }
            }
            float* dst = outp + s * LSTRIDE + ((MODE == 2) ? 256 : 0) + cbase;
            *(float4*)dst       = *(float4*)o;
            *(float4*)(dst + 4) = *(float4*)(o + 4);
        }
    }
}

__global__ void __launch_bounds__(NTHREADS, 1) covnet_kernel(
    const float* __restrict__ P_prev,
    const float* __restrict__ W1, const float* __restrict__ b1,
    const float* __restrict__ W2, const float* __restrict__ b2,
    const float* __restrict__ W3, const float* __restrict__ b3,
    const float* __restrict__ Q, float* __restrict__ out)
{
    extern __shared__ float sm[];
    const int tid = threadIdx.x;
    const int tx = tid & 31;
    const int wp = tid >> 5;
    const int sbase = 32 * (wp & 1) + 4 * (tx & 7);
    const int cg = wp >> 1;
    const int cbase = 32 * cg + 8 * (tx >> 3);
    const size_t b0 = (size_t)blockIdx.x * BM;

    // Q -> smem
    if (tid < NXD * NXD) sm[OFF_Q + tid] = Q[tid];
    if (tid + 512 < NXD * NXD) sm[OFF_Q + tid + 512] = Q[tid + 512];

    // gather diagonal (transposed): sXt[d*HSTR + s] = log(clip(P_prev[s,d,d]))
    for (int i = tid; i < NXD * BM; i += NTHREADS) {
        int d = i >> 6, s = i & 63;
        float v = P_prev[(b0 + (size_t)s) * 1024 + d * 33];
        sm[OFF_X + d * HSTR + s] = __logf(fmaxf(v, 1e-6f));
    }
    __syncthreads();

    gemm_f2<32,  0>(sm, W1,       HID,  b1,       sm + OFF_X,  sm + OFF_H1, sbase, cbase, cg);
    gemm_f2<256, 0>(sm, W2,       HID,  b2,       sm + OFF_H1, sm + OFF_H2, sbase, cbase, cg);
    gemm_f2<256, 1>(sm, W3,       NOUT, b3,       sm + OFF_H2, sm + OFF_L,  sbase, cbase, cg);
    gemm_f2<256, 2>(sm, W3 + 256, NOUT, b3 + 256, sm + OFF_H2, sm + OFF_L,  sbase, cbase, cg);
    __syncthreads();

    // ====== GEMM3 tail: cols [512, 528) ======
    {
        // stage W3 tail [256 x 16] into W0+W1 (4096 floats contiguous)
        #pragma unroll
        for (int rep = 0; rep < 2; rep++) {
            int idx = tid + rep * 512;
            int k = idx >> 2, c4 = idx & 3;
            float4 w = *(const float4*)&W3[(size_t)k * NOUT + 512 + 4 * c4];
            *(float4*)&sm[OFF_W0 + k * 16 + 4 * c4] = w;
        }
        __syncthreads();
        const int s = tid >> 3;            // 0..63
        const int c = tid & 7;             // cols c and c+8
        float a0 = b3[512 + c], a1 = b3[520 + c];
        const float* hr = sm + OFF_H2;
        const float* wt = sm + OFF_W0;
        #pragma unroll 8
        for (int k = 0; k < HID; k++) {
            float hv = hr[k * HSTR + s];
            a0 += hv * wt[k * 16 + c];
            a1 += hv * wt[k * 16 + c + 8];
        }
        sm[OFF_L + s * LSTRIDE + 512 + c]     = 0.1f * ftanh(a0);
        sm[OFF_L + s * LSTRIDE + 512 + c + 8] = 0.1f * ftanh(a1);
    }
    __syncthreads();

    // ================= P = L * L^T + Q =================
    // warp handles 4 samples; lane k owns output column k.
    {
        const int k = tx;
        const int s0 = wp * 4;
        const int kbase = 32 + (k * (k - 1)) / 2;
        #pragma unroll
        for (int ss = 0; ss < 4; ss++) {
            const int s = s0 + ss;
            const float* Lr = sm + OFF_L + s * LSTRIDE;
            float Lk[32];
            #pragma unroll
            for (int j = 0; j < 32; j++) {
                float v = 0.f;
                if (j < k)       v = Lr[kbase + j];
                else if (j == k) v = Lr[k];
                Lk[j] = v;
            }
            float* Po = out + (b0 + (size_t)s) * 1024;
            #pragma unroll
            for (int i = 0; i < 32; i++) {
                float a = sm[OFF_Q + i * 32 + k];
                const int ib = 32 + (i * (i - 1)) / 2;
                #pragma unroll
                for (int j = 0; j < i; j++) {
                    float lij = Lr[ib + j];      // warp-uniform broadcast
                    if (j <= k) a += lij * Lk[j];
                }
                float lii = Lr[i];
                if (i <= k) a += lii * Lk[i];
                Po[i * 32 + k] = a;
            }
        }
    }
}

extern "C" void kernel_launch(void* const* d_in, const int* in_sizes, int n_in,
                              void* d_out, int out_size) {
    const float* P_prev = (const float*)d_in[0];
    const float* W1 = (const float*)d_in[1];
    const float* b1 = (const float*)d_in[2];
    const float* W2 = (const float*)d_in[3];
    const float* b2 = (const float*)d_in[4];
    const float* W3 = (const float*)d_in[5];
    const float* b3 = (const float*)d_in[6];
    const float* Q  = (const float*)d_in[7];
    float* out = (float*)d_out;

    const int B = in_sizes[0] / (NXD * NXD);   // 65536
    const int grid = B / BM;                   // 1024

    cudaFuncSetAttribute(covnet_kernel,
                         cudaFuncAttributeMaxDynamicSharedMemorySize,
                         SMEM_FLOATS * sizeof(float));

    covnet_kernel<<<grid, NTHREADS, SMEM_FLOATS * sizeof(float)>>>(
        P_prev, W1, b1, W2, b2, W3, b3, Q, out);
}

// round 6
// speedup vs baseline: 1.1098x; 1.0593x over previous
#include <cuda_runtime.h>
#include <math.h>

#define NXD 32
#define HID 256
#define NOUT 528
#define BM 32
#define NTHREADS 512
#define KC 8
#define HSTR 36
#define LSTRIDE 532

// shared layout (float offsets), total 28288 floats = 113152 B (2 blocks/SM)
#define OFF_H2 0        // 256*36 = 9216
#define OFF_W  9216     // 8*256  = 2048 (single buffer)
#define OFF_X  11264    // 32*36  = 1152  (dead after G1)
#define OFF_H1 12416    // 256*36 = 9216  (dead after G2)
#define OFF_L  11264    // 32*532 = 17024 (overlays X+H1, extends to 28288)
#define SMEM_FLOATS 28288

typedef unsigned long long u64;

__device__ __forceinline__ u64 pk2(float lo, float hi) {
    u64 d; asm("mov.b64 %0, {%1, %2};" : "=l"(d) : "f"(lo), "f"(hi)); return d;
}
__device__ __forceinline__ void fma2(u64& d, u64 a, u64 b) {
    asm("fma.rn.f32x2 %0, %1, %2, %0;" : "+l"(d) : "l"(a), "l"(b));
}
__device__ __forceinline__ float2 up2(u64 d) {
    float2 r; asm("mov.b64 {%0, %1}, %2;" : "=f"(r.x), "=f"(r.y) : "l"(d)); return r;
}
__device__ __forceinline__ u64 swp2(u64 d) {        // (lo,hi) -> (hi,lo)
    float2 r = up2(d); return pk2(r.y, r.x);
}
__device__ __forceinline__ float ftanh(float x) {
    x = fminf(fmaxf(x, -15.f), 15.f);
    float e = __expf(2.f * x);
    return __fdividef(e - 1.f, e + 1.f);
}
__device__ __forceinline__ float fsplus(float v) {
    float sp = (v > 20.f) ? v : __logf(1.f + __expf(v));
    return fminf(fmaxf(sp + 0.01f, 0.01f), 100.f);
}

// stage one 8x256 chunk (2048 floats): 512 threads x float4
__device__ __forceinline__ void stage_ld(const float* __restrict__ Wg, int ldw,
                                         int ch, float4& rg) {
    int r = threadIdx.x >> 6, c4 = threadIdx.x & 63;
    rg = *(const float4*)&Wg[(size_t)(ch * 8 + r) * ldw + 4 * c4];
}
__device__ __forceinline__ void stage_st(float* buf, float4 rg) {
    int r = threadIdx.x >> 6, c4 = threadIdx.x & 63;
    *(float4*)&buf[r * 256 + 4 * c4] = rg;
}

// Warp tile: 32 samples x 16 cols (warp wp owns cols 16wp..16wp+15).
// Lane: r=tx&7 -> samples sbase=4r..4r+3 ; c=tx>>3 -> cols cbase=16wp+4c..+3.
// Mixed f32x2 packing:
//   accP[sp][j] = (P[sa][c0], P[sb][c1]),  accQ[sp][j] = (P[sa][c1], P[sb][c0])
//   sa=sbase+2sp, sb=sa+1, c0=cbase+2j, c1=c0+1.
// h operand = raw ulonglong2 view of LDS.128 (no movs); w operand needs 1 swap per pair.
// MODE 0: tanh -> transposed outp[col*HSTR + s]
// MODE 1: GEMM3 cols [0,256): wp<2 -> softplus else 0.1*tanh -> sL[s*LSTRIDE + col]
// MODE 2: GEMM3 cols [256,512): 0.1*tanh -> sL[s*LSTRIDE + 256 + col]
template<int KTOT, int MODE>
__device__ __forceinline__ void gemm_f2(
    float* sm, const float* __restrict__ Wg, int ldw,
    const float* __restrict__ bias,
    const float* sHin, float* outp, int sbase, int cbase, int wp)
{
    const int NCH = KTOT / KC;
    float* sW = sm + OFF_W;

    u64 accP[2][2], accQ[2][2];
    {
        float4 b4 = *(const float4*)&bias[cbase];
        u64 bp0 = pk2(b4.x, b4.y), bq0 = pk2(b4.y, b4.x);
        u64 bp1 = pk2(b4.z, b4.w), bq1 = pk2(b4.w, b4.z);
        accP[0][0] = bp0; accP[1][0] = bp0; accQ[0][0] = bq0; accQ[1][0] = bq0;
        accP[0][1] = bp1; accP[1][1] = bp1; accQ[0][1] = bq1; accQ[1][1] = bq1;
    }

    float4 rg;
    stage_ld(Wg, ldw, 0, rg);
    stage_st(sW, rg);
    __syncthreads();

    for (int ch = 0; ch < NCH; ch++) {
        if (ch + 1 < NCH) stage_ld(Wg, ldw, ch + 1, rg);
        const int kc = ch * KC;
        #pragma unroll
        for (int kk = 0; kk < KC; kk++) {
            ulonglong2 hv = *(const ulonglong2*)&sHin[(kc + kk) * HSTR + sbase];
            ulonglong2 wv = *(const ulonglong2*)&sW[kk * 256 + cbase];
            u64 w01s = swp2(wv.x);
            u64 w23s = swp2(wv.y);
            fma2(accP[0][0], hv.x, wv.x);
            fma2(accQ[0][0], hv.x, w01s);
            fma2(accP[0][1], hv.x, wv.y);
            fma2(accQ[0][1], hv.x, w23s);
            fma2(accP[1][0], hv.y, wv.x);
            fma2(accQ[1][0], hv.y, w01s);
            fma2(accP[1][1], hv.y, wv.y);
            fma2(accQ[1][1], hv.y, w23s);
        }
        __syncthreads();
        if (ch + 1 < NCH) { stage_st(sW, rg); __syncthreads(); }
    }

    // epilogue
    if (MODE == 0) {
        #pragma unroll
        for (int j = 0; j < 2; j++) {
            float2 P0 = up2(accP[0][j]), Q0 = up2(accQ[0][j]);
            float2 P1 = up2(accP[1][j]), Q1 = up2(accQ[1][j]);
            int c0 = cbase + 2 * j;
            float4 v0 = { ftanh(P0.x), ftanh(Q0.y), ftanh(P1.x), ftanh(Q1.y) };
            float4 v1 = { ftanh(Q0.x), ftanh(P0.y), ftanh(Q1.x), ftanh(P1.y) };
            *(float4*)&outp[c0 * HSTR + sbase]       = v0;
            *(float4*)&outp[(c0 + 1) * HSTR + sbase] = v1;
        }
    } else {
        #pragma unroll
        for (int sp = 0; sp < 2; sp++) {
            float2 p0 = up2(accP[sp][0]), q0 = up2(accQ[sp][0]);
            float2 p1 = up2(accP[sp][1]), q1 = up2(accQ[sp][1]);
            float ea[4] = { p0.x, q0.x, p1.x, q1.x };   // sample sbase+2sp
            float eb[4] = { q0.y, p0.y, q1.y, p1.y };   // sample sbase+2sp+1
            float oa[4], ob[4];
            bool dg = (MODE == 1) && (wp < 2);           // warp-uniform
            #pragma unroll
            for (int m = 0; m < 4; m++) {
                oa[m] = dg ? fsplus(ea[m]) : 0.1f * ftanh(ea[m]);
                ob[m] = dg ? fsplus(eb[m]) : 0.1f * ftanh(eb[m]);
            }
            const int off = (MODE == 2) ? 256 : 0;
            int sa = sbase + 2 * sp;
            *(float4*)&outp[sa * LSTRIDE + off + cbase]       = *(float4*)oa;
            *(float4*)&outp[(sa + 1) * LSTRIDE + off + cbase] = *(float4*)ob;
        }
    }
}

__global__ void __launch_bounds__(NTHREADS, 2) covnet_kernel(
    const float* __restrict__ P_prev,
    const float* __restrict__ W1, const float* __restrict__ b1,
    const float* __restrict__ W2, const float* __restrict__ b2,
    const float* __restrict__ W3, const float* __restrict__ b3,
    const float* __restrict__ Q, float* __restrict__ out)
{
    extern __shared__ float sm[];
    const int tid = threadIdx.x;
    const int tx = tid & 31;
    const int wp = tid >> 5;
    const int sbase = 4 * (tx & 7);
    const int cbase = 16 * wp + 4 * (tx >> 3);
    const size_t b0 = (size_t)blockIdx.x * BM;

    // gather diagonal (transposed): sXt[d*HSTR + s] = log(clip(P_prev[s,d,d]))
    for (int i = tid; i < NXD * BM; i += NTHREADS) {
        int d = i >> 5, s = i & 31;
        float v = P_prev[(b0 + (size_t)s) * 1024 + d * 33];
        sm[OFF_X + d * HSTR + s] = __logf(fmaxf(v, 1e-6f));
    }
    __syncthreads();

    gemm_f2<32,  0>(sm, W1,       HID,  b1,       sm + OFF_X,  sm + OFF_H1, sbase, cbase, wp);
    gemm_f2<256, 0>(sm, W2,       HID,  b2,       sm + OFF_H1, sm + OFF_H2, sbase, cbase, wp);
    gemm_f2<256, 1>(sm, W3,       NOUT, b3,       sm + OFF_H2, sm + OFF_L,  sbase, cbase, wp);
    gemm_f2<256, 2>(sm, W3 + 256, NOUT, b3 + 256, sm + OFF_H2, sm + OFF_L,  sbase, cbase, wp);

    // ====== GEMM3 tail: cols [512, 528), weights straight from L2 ======
    {
        const int s = tid >> 4;            // 0..31
        const int c = tid & 15;            // 0..15
        float a = __ldg(&b3[512 + c]);
        const float* hr = sm + OFF_H2;
        #pragma unroll 8
        for (int k = 0; k < HID; k++)
            a += hr[k * HSTR + s] * __ldg(&W3[(size_t)k * NOUT + 512 + c]);
        sm[OFF_L + s * LSTRIDE + 512 + c] = 0.1f * ftanh(a);
    }
    __syncthreads();

    // ================= P = L * L^T + Q =================
    // warp handles 2 samples; lane k owns output column k. Q via L2 (__ldg).
    {
        const int k = tx;
        const int kbase = 32 + (k * (k - 1)) / 2;
        #pragma unroll
        for (int ss = 0; ss < 2; ss++) {
            const int s = 2 * wp + ss;
            const float* Lr = sm + OFF_L + s * LSTRIDE;
            float Lk[32];
            #pragma unroll
            for (int j = 0; j < 32; j++) {
                float v = 0.f;
                if (j < k)       v = Lr[kbase + j];
                else if (j == k) v = Lr[k];
                Lk[j] = v;
            }
            float* Po = out + (b0 + (size_t)s) * 1024;
            #pragma unroll
            for (int i = 0; i < 32; i++) {
                float a = __ldg(&Q[i * 32 + k]);
                const int ib = 32 + (i * (i - 1)) / 2;
                #pragma unroll
                for (int j = 0; j < i; j++) {
                    float lij = Lr[ib + j];      // warp-uniform broadcast
                    if (j <= k) a += lij * Lk[j];
                }
                float lii = Lr[i];
                if (i <= k) a += lii * Lk[i];
                Po[i * 32 + k] = a;
            }
        }
    }
}

extern "C" void kernel_launch(void* const* d_in, const int* in_sizes, int n_in,
                              void* d_out, int out_size) {
    const float* P_prev = (const float*)d_in[0];
    const float* W1 = (const float*)d_in[1];
    const float* b1 = (const float*)d_in[2];
    const float* W2 = (const float*)d_in[3];
    const float* b2 = (const float*)d_in[4];
    const float* W3 = (const float*)d_in[5];
    const float* b3 = (const float*)d_in[6];
    const float* Q  = (const float*)d_in[7];
    float* out = (float*)d_out;

    const int B = in_sizes[0] / (NXD * NXD);   // 65536
    const int grid = B / BM;                   // 2048

    cudaFuncSetAttribute(covnet_kernel,
                         cudaFuncAttributeMaxDynamicSharedMemorySize,
                         SMEM_FLOATS * sizeof(float));

    covnet_kernel<<<grid, NTHREADS, SMEM_FLOATS * sizeof(float)>>>(
        P_prev, W1, b1, W2, b2, W3, b3, Q, out);
}

// round 7
// speedup vs baseline: 1.1114x; 1.0014x over previous
#include <cuda_runtime.h>
#include <math.h>

#define NXD 32
#define HID 256
#define NOUT 528
#define BM 32
#define NTHREADS 512
#define KC 8
#define HSTR 36
#define LSTRIDE 532

// shared layout (float offsets), total 28288 floats = 113152 B (2 blocks/SM)
#define OFF_H2 0        // 256*36 = 9216
#define OFF_W  9216     // 8*256  = 2048 (single buffer)
#define OFF_X  11264    // 32*36  = 1152  (dead after G1)
#define OFF_H1 12416    // 256*36 = 9216  (dead after G2)
#define OFF_L  11264    // 32*532 = 17024 (overlays X+H1, extends to 28288)
#define SMEM_FLOATS 28288

typedef unsigned long long u64;

__device__ __forceinline__ u64 pk2(float lo, float hi) {
    u64 d; asm("mov.b64 %0, {%1, %2};" : "=l"(d) : "f"(lo), "f"(hi)); return d;
}
__device__ __forceinline__ void fma2(u64& d, u64 a, u64 b) {
    asm("fma.rn.f32x2 %0, %1, %2, %0;" : "+l"(d) : "l"(a), "l"(b));
}
__device__ __forceinline__ float2 up2(u64 d) {
    float2 r; asm("mov.b64 {%0, %1}, %2;" : "=f"(r.x), "=f"(r.y) : "l"(d)); return r;
}
__device__ __forceinline__ u64 swp2(u64 d) {        // (lo,hi) -> (hi,lo)
    float2 r = up2(d); return pk2(r.y, r.x);
}
__device__ __forceinline__ float ftanh(float x) {
    x = fminf(fmaxf(x, -15.f), 15.f);
    float e = __expf(2.f * x);
    return __fdividef(e - 1.f, e + 1.f);
}
__device__ __forceinline__ float fsplus(float v) {
    float sp = (v > 20.f) ? v : __logf(1.f + __expf(v));
    return fminf(fmaxf(sp + 0.01f, 0.01f), 100.f);
}

// stage one 8x256 chunk (2048 floats): 512 threads x float4
__device__ __forceinline__ void stage_ld(const float* __restrict__ Wg, int ldw,
                                         int ch, float4& rg) {
    int r = threadIdx.x >> 6, c4 = threadIdx.x & 63;
    rg = *(const float4*)&Wg[(size_t)(ch * 8 + r) * ldw + 4 * c4];
}
__device__ __forceinline__ void stage_st(float* buf, float4 rg) {
    int r = threadIdx.x >> 6, c4 = threadIdx.x & 63;
    *(float4*)&buf[r * 256 + 4 * c4] = rg;
}

// Warp tile: 32 samples x 16 cols (warp wp owns cols 16wp..16wp+15).
// Lane: r=tx&7 -> samples sbase=4r..4r+3 ; c=tx>>3 -> cols cbase=16wp+4c..+3.
// Mixed f32x2 packing:
//   accP[sp][j] = (P[sa][c0], P[sb][c1]),  accQ[sp][j] = (P[sa][c1], P[sb][c0])
//   sa=sbase+2sp, sb=sa+1, c0=cbase+2j, c1=c0+1.
// h operand = raw ulonglong2 view of LDS.128 (no movs); w operand needs 1 swap per pair.
// MODE 0: tanh -> transposed outp[col*HSTR + s]
// MODE 1: GEMM3 cols [0,256): wp<2 -> softplus else 0.1*tanh -> sL[s*LSTRIDE + col]
// MODE 2: GEMM3 cols [256,512): 0.1*tanh -> sL[s*LSTRIDE + 256 + col]
template<int KTOT, int MODE>
__device__ __forceinline__ void gemm_f2(
    float* sm, const float* __restrict__ Wg, int ldw,
    const float* __restrict__ bias,
    const float* sHin, float* outp, int sbase, int cbase, int wp)
{
    const int NCH = KTOT / KC;
    float* sW = sm + OFF_W;

    u64 accP[2][2], accQ[2][2];
    {
        float4 b4 = *(const float4*)&bias[cbase];
        u64 bp0 = pk2(b4.x, b4.y), bq0 = pk2(b4.y, b4.x);
        u64 bp1 = pk2(b4.z, b4.w), bq1 = pk2(b4.w, b4.z);
        accP[0][0] = bp0; accP[1][0] = bp0; accQ[0][0] = bq0; accQ[1][0] = bq0;
        accP[0][1] = bp1; accP[1][1] = bp1; accQ[0][1] = bq1; accQ[1][1] = bq1;
    }

    float4 rg;
    stage_ld(Wg, ldw, 0, rg);
    stage_st(sW, rg);
    __syncthreads();

    for (int ch = 0; ch < NCH; ch++) {
        if (ch + 1 < NCH) stage_ld(Wg, ldw, ch + 1, rg);
        const int kc = ch * KC;
        #pragma unroll
        for (int kk = 0; kk < KC; kk++) {
            ulonglong2 hv = *(const ulonglong2*)&sHin[(kc + kk) * HSTR + sbase];
            ulonglong2 wv = *(const ulonglong2*)&sW[kk * 256 + cbase];
            u64 w01s = swp2(wv.x);
            u64 w23s = swp2(wv.y);
            fma2(accP[0][0], hv.x, wv.x);
            fma2(accQ[0][0], hv.x, w01s);
            fma2(accP[0][1], hv.x, wv.y);
            fma2(accQ[0][1], hv.x, w23s);
            fma2(accP[1][0], hv.y, wv.x);
            fma2(accQ[1][0], hv.y, w01s);
            fma2(accP[1][1], hv.y, wv.y);
            fma2(accQ[1][1], hv.y, w23s);
        }
        __syncthreads();
        if (ch + 1 < NCH) { stage_st(sW, rg); __syncthreads(); }
    }

    // epilogue
    if (MODE == 0) {
        #pragma unroll
        for (int j = 0; j < 2; j++) {
            float2 P0 = up2(accP[0][j]), Q0 = up2(accQ[0][j]);
            float2 P1 = up2(accP[1][j]), Q1 = up2(accQ[1][j]);
            int c0 = cbase + 2 * j;
            float4 v0 = { ftanh(P0.x), ftanh(Q0.y), ftanh(P1.x), ftanh(Q1.y) };
            float4 v1 = { ftanh(Q0.x), ftanh(P0.y), ftanh(Q1.x), ftanh(P1.y) };
            *(float4*)&outp[c0 * HSTR + sbase]       = v0;
            *(float4*)&outp[(c0 + 1) * HSTR + sbase] = v1;
        }
    } else {
        #pragma unroll
        for (int sp = 0; sp < 2; sp++) {
            float2 p0 = up2(accP[sp][0]), q0 = up2(accQ[sp][0]);
            float2 p1 = up2(accP[sp][1]), q1 = up2(accQ[sp][1]);
            float ea[4] = { p0.x, q0.x, p1.x, q1.x };   // sample sbase+2sp
            float eb[4] = { q0.y, p0.y, q1.y, p1.y };   // sample sbase+2sp+1
            float oa[4], ob[4];
            bool dg = (MODE == 1) && (wp < 2);           // warp-uniform
            #pragma unroll
            for (int m = 0; m < 4; m++) {
                oa[m] = dg ? fsplus(ea[m]) : 0.1f * ftanh(ea[m]);
                ob[m] = dg ? fsplus(eb[m]) : 0.1f * ftanh(eb[m]);
            }
            const int off = (MODE == 2) ? 256 : 0;
            int sa = sbase + 2 * sp;
            *(float4*)&outp[sa * LSTRIDE + off + cbase]       = *(float4*)oa;
            *(float4*)&outp[(sa + 1) * LSTRIDE + off + cbase] = *(float4*)ob;
        }
    }
}

__global__ void __launch_bounds__(NTHREADS, 2) covnet_kernel(
    const float* __restrict__ P_prev,
    const float* __restrict__ W1, const float* __restrict__ b1,
    const float* __restrict__ W2, const float* __restrict__ b2,
    const float* __restrict__ W3, const float* __restrict__ b3,
    const float* __restrict__ Q, float* __restrict__ out)
{
    extern __shared__ float sm[];
    const int tid = threadIdx.x;
    const int tx = tid & 31;
    const int wp = tid >> 5;
    const int sbase = 4 * (tx & 7);
    const int cbase = 16 * wp + 4 * (tx >> 3);
    const size_t b0 = (size_t)blockIdx.x * BM;

    // gather diagonal (transposed): sXt[d*HSTR + s] = log(clip(P_prev[s,d,d]))
    for (int i = tid; i < NXD * BM; i += NTHREADS) {
        int d = i >> 5, s = i & 31;
        float v = P_prev[(b0 + (size_t)s) * 1024 + d * 33];
        sm[OFF_X + d * HSTR + s] = __logf(fmaxf(v, 1e-6f));
    }
    __syncthreads();

    gemm_f2<32,  0>(sm, W1,       HID,  b1,       sm + OFF_X,  sm + OFF_H1, sbase, cbase, wp);
    gemm_f2<256, 0>(sm, W2,       HID,  b2,       sm + OFF_H1, sm + OFF_H2, sbase, cbase, wp);
    gemm_f2<256, 1>(sm, W3,       NOUT, b3,       sm + OFF_H2, sm + OFF_L,  sbase, cbase, wp);
    gemm_f2<256, 2>(sm, W3 + 256, NOUT, b3 + 256, sm + OFF_H2, sm + OFF_L,  sbase, cbase, wp);

    // ====== GEMM3 tail: cols [512, 528), weights straight from L2 ======
    {
        const int s = tid >> 4;            // 0..31
        const int c = tid & 15;            // 0..15
        float a = __ldg(&b3[512 + c]);
        const float* hr = sm + OFF_H2;
        #pragma unroll 8
        for (int k = 0; k < HID; k++)
            a += hr[k * HSTR + s] * __ldg(&W3[(size_t)k * NOUT + 512 + c]);
        sm[OFF_L + s * LSTRIDE + 512 + c] = 0.1f * ftanh(a);
    }
    __syncthreads();

    // ================= P = L * L^T + Q =================
    // warp handles 2 samples; lane k owns output column k. Q via L2 (__ldg).
    {
        const int k = tx;
        const int kbase = 32 + (k * (k - 1)) / 2;
        #pragma unroll
        for (int ss = 0; ss < 2; ss++) {
            const int s = 2 * wp + ss;
            const float* Lr = sm + OFF_L + s * LSTRIDE;
            float Lk[32];
            #pragma unroll
            for (int j = 0; j < 32; j++) {
                float v = 0.f;
                if (j < k)       v = Lr[kbase + j];
                else if (j == k) v = Lr[k];
                Lk[j] = v;
            }
            float* Po = out + (b0 + (size_t)s) * 1024;
            #pragma unroll
            for (int i = 0; i < 32; i++) {
                float a = __ldg(&Q[i * 32 + k]);
                const int ib = 32 + (i * (i - 1)) / 2;
                #pragma unroll
                for (int j = 0; j < i; j++) {
                    float lij = Lr[ib + j];      // warp-uniform broadcast
                    if (j <= k) a += lij * Lk[j];
                }
                float lii = Lr[i];
                if (i <= k) a += lii * Lk[i];
                Po[i * 32 + k] = a;
            }
        }
    }
}

extern "C" void kernel_launch(void* const* d_in, const int* in_sizes, int n_in,
                              void* d_out, int out_size) {
    const float* P_prev = (const float*)d_in[0];
    const float* W1 = (const float*)d_in[1];
    const float* b1 = (const float*)d_in[2];
    const float* W2 = (const float*)d_in[3];
    const float* b2 = (const float*)d_in[4];
    const float* W3 = (const float*)d_in[5];
    const float* b3 = (const float*)d_in[6];
    const float* Q  = (const float*)d_in[7];
    float* out = (float*)d_out;

    const int B = in_sizes[0] / (NXD * NXD);   // 65536
    const int grid = B / BM;                   // 2048

    cudaFuncSetAttribute(covnet_kernel,
                         cudaFuncAttributeMaxDynamicSharedMemorySize,
                         SMEM_FLOATS * sizeof(float));

    covnet_kernel<<<grid, NTHREADS, SMEM_FLOATS * sizeof(float)>>>(
        P_prev, W1, b1, W2, b2, W3, b3, Q, out);
}